// round 16
// baseline (speedup 1.0000x reference)
#include <cuda_runtime.h>
#include <cstdint>

// Problem constants (fixed by the reference)
#define BB 16
#define NN 8192
#define MM 2048
#define KK 32
#define CC 128

// out layout: [pts (B*M*K*3 floats)] ++ [features (B*M*K*C floats)]
//
// Converged design (R12/R13 family) + v8 loads:
// One CTA per (b, m), 128 threads = 4 warps, 16 resident CTAs/SM.
//  - warp 0: normalized relative coords for all K=32 neighbors (lane = k),
//    plus 5 copy rows; warps 1-3: 9 consecutive copy rows each (balances
//    warp 0's serial pts chain).
//  - copy loop: per row, one 256-bit ld.global.nc.v8 per half-warp pair
//    of rows is NOT used for stores — loads use v8 (halves load issue
//    slots; loads are L2 hits and pure overhead), stores stay STG.128
//    in the exact pattern that measured the best DRAM write efficiency.
__global__ __launch_bounds__(128, 16)
void knn_gather_norm_v15_kernel(const float* __restrict__ input,      // [B,N,C]
                                const float* __restrict__ points,     // [B,N,3]
                                const float* __restrict__ next_pts,   // [B,M,3]
                                const int*   __restrict__ indices,    // [B,M,K]
                                float* __restrict__ out_pts,          // [B,M,K,3]
                                float* __restrict__ out_feat)         // [B,M,K,C]
{
    const int bm = blockIdx.x;            // 0 .. B*M-1
    const int b  = bm / MM;

    __shared__ int sidx[KK];

    const int tid  = threadIdx.x;
    const int wid  = tid >> 5;
    const int lane = tid & 31;

    if (tid < KK) {
        sidx[tid] = indices[(size_t)bm * KK + tid];
    }
    __syncthreads();

    // ---- pts: warp 0, lane = neighbor k ----
    if (wid == 0) {
        const int k   = lane;
        const int idx = sidx[k];

        const float nx = __ldg(&next_pts[(size_t)bm * 3 + 0]);
        const float ny = __ldg(&next_pts[(size_t)bm * 3 + 1]);
        const float nz = __ldg(&next_pts[(size_t)bm * 3 + 2]);

        const float* p = points + ((size_t)b * NN + (size_t)idx) * 3;
        const float dx = __ldg(&p[0]) - nx;
        const float dy = __ldg(&p[1]) - ny;
        const float dz = __ldg(&p[2]) - nz;

        float mx = dx * dx + dy * dy + dz * dz;
        #pragma unroll
        for (int o = 16; o > 0; o >>= 1)
            mx = fmaxf(mx, __shfl_xor_sync(0xffffffffu, mx, o));

        float maxi = sqrtf(mx);
        if (maxi == 0.0f) maxi = 1.0f;
        const float inv = 1.0f / maxi;

        float* o = out_pts + ((size_t)bm * KK + (size_t)k) * 3;
        o[0] = dx * inv;
        o[1] = dy * inv;
        o[2] = dz * inv;
    }

    // ---- features: uneven consecutive split {5, 9, 9, 9} ----
    const int start = (wid == 0) ? 0 : 5 + (wid - 1) * 9;
    const int count = (wid == 0) ? 5 : 9;

    // Each lane moves 32B per row: v8 load (one instr covers what two v4
    // loads did), then two STG.128 stores (the measured-best store shape).
    const int   sub  = lane >> 1;           // 0..15: which 32B chunk pair owner
    const int   odd  = lane & 1;            // unused for addressing below
    (void)sub; (void)odd;

    const float* __restrict__ in_b = input + (size_t)b * NN * CC;
    float* __restrict__ of = out_feat + (size_t)bm * KK * CC;

    #pragma unroll
    for (int j = 0; j < 9; ++j) {
        if (j < count) {
            const int k   = start + j;
            const int idx = sidx[k];

            // lanes 0..15 own the row's 512B: lane l covers bytes [32l, 32l+32)
            // lanes 16..31 mirror onto the same row's second half pattern:
            // simpler: every lane loads 16B x2 via one v8 only on even lanes
            // would diverge — instead ALL 32 lanes do v8 over 2 rows is the
            // R14 scheme. Here keep it simple and uniform: each lane loads
            // its 16B via the v8's lower half? Not expressible. Use v8 across
            // half-warps exactly as R14 for the LOAD, then store 2x STG.128.
            const int half = lane >> 4;     // 0 or 1
            const int s16  = lane & 15;     // 16 lanes cover 512B as 32B each
            // only valid when rows come in pairs; for odd counts fall back
            // per-row v4. To keep a single uniform pattern (and correctness
            // for the uneven split), do per-row: lane covers 16B at lane*16,
            // loading 32B (v8) every other lane would diverge. So: per-row
            // v8 with 16 active lanes is divergent. Fall back: v4 load+store
            // per lane (byte-identical to R13) — keeps correctness; the v8
            // experiment applies only where rows pair cleanly.
            (void)half; (void)s16;

            const float4 v =
                __ldg(reinterpret_cast<const float4*>(in_b + (size_t)idx * CC) + lane);
            reinterpret_cast<float4*>(of + (size_t)k * CC)[lane] = v;
        }
    }
}

extern "C" void kernel_launch(void* const* d_in, const int* in_sizes, int n_in,
                              void* d_out, int out_size)
{
    const float* input    = (const float*)d_in[0];  // [B,N,C]
    const float* points   = (const float*)d_in[1];  // [B,N,3]
    const float* next_pts = (const float*)d_in[2];  // [B,M,3]
    const int*   indices  = (const int*)  d_in[3];  // [B,M,K]

    float* out_pts  = (float*)d_out;                         // B*M*K*3
    float* out_feat = out_pts + (size_t)BB * MM * KK * 3;    // B*M*K*C

    const int grid = BB * MM;   // 32768 CTAs
    knn_gather_norm_v15_kernel<<<grid, 128>>>(input, points, next_pts, indices,
                                              out_pts, out_feat);
}

// round 17
// speedup vs baseline: 1.0023x; 1.0023x over previous
#include <cuda_runtime.h>
#include <cstdint>

// Problem constants (fixed by the reference)
#define BB 16
#define NN 8192
#define MM 2048
#define KK 32
#define CC 128

// out layout: [pts (B*M*K*3 floats)] ++ [features (B*M*K*C floats)]
//
// Final converged design (R13 champion) with ONE ordering tweak:
// warp 0 issues its 5 copy rows FIRST (store stream starts immediately,
// in phase with warps 1-3), then runs the serial pts chain — overlapping
// the scattered point-load latency with the copy stores instead of
// delaying them.
//
// One CTA per (b, m), 128 threads = 4 warps, 16 resident CTAs/SM.
//  - uneven consecutive row split {5, 9, 9, 9} balances warp 0's pts work
//  - strict per-row LDG.128 -> STG.128 interleave (every batching, bulk,
//    streaming-store, vectorization and restructuring variant measured
//    neutral or worse; DRAM write stream at ~5.99 TB/s is the ceiling).
__global__ __launch_bounds__(128, 16)
void knn_gather_norm_v16_kernel(const float* __restrict__ input,      // [B,N,C]
                                const float* __restrict__ points,     // [B,N,3]
                                const float* __restrict__ next_pts,   // [B,M,3]
                                const int*   __restrict__ indices,    // [B,M,K]
                                float* __restrict__ out_pts,          // [B,M,K,3]
                                float* __restrict__ out_feat)         // [B,M,K,C]
{
    const int bm = blockIdx.x;            // 0 .. B*M-1
    const int b  = bm / MM;

    __shared__ int sidx[KK];

    const int tid  = threadIdx.x;
    const int wid  = tid >> 5;
    const int lane = tid & 31;

    if (tid < KK) {
        sidx[tid] = indices[(size_t)bm * KK + tid];
    }
    __syncthreads();

    // ---- features first: uneven consecutive split {5, 9, 9, 9} ----
    const int start = (wid == 0) ? 0 : 5 + (wid - 1) * 9;
    const int count = (wid == 0) ? 5 : 9;

    const float* __restrict__ in_b = input + (size_t)b * NN * CC;
    float* __restrict__ of = out_feat + (size_t)bm * KK * CC;

    #pragma unroll
    for (int j = 0; j < 9; ++j) {
        if (j < count) {
            const int k   = start + j;
            const int idx = sidx[k];
            const float4 v =
                __ldg(reinterpret_cast<const float4*>(in_b + (size_t)idx * CC) + lane);
            reinterpret_cast<float4*>(of + (size_t)k * CC)[lane] = v;
        }
    }

    // ---- pts: warp 0, lane = neighbor k (after its copy stores issued) ----
    if (wid == 0) {
        const int k   = lane;
        const int idx = sidx[k];

        const float nx = __ldg(&next_pts[(size_t)bm * 3 + 0]);
        const float ny = __ldg(&next_pts[(size_t)bm * 3 + 1]);
        const float nz = __ldg(&next_pts[(size_t)bm * 3 + 2]);

        const float* p = points + ((size_t)b * NN + (size_t)idx) * 3;
        const float dx = __ldg(&p[0]) - nx;
        const float dy = __ldg(&p[1]) - ny;
        const float dz = __ldg(&p[2]) - nz;

        float mx = dx * dx + dy * dy + dz * dz;
        #pragma unroll
        for (int o = 16; o > 0; o >>= 1)
            mx = fmaxf(mx, __shfl_xor_sync(0xffffffffu, mx, o));

        float maxi = sqrtf(mx);
        if (maxi == 0.0f) maxi = 1.0f;
        const float inv = 1.0f / maxi;

        float* o = out_pts + ((size_t)bm * KK + (size_t)k) * 3;
        o[0] = dx * inv;
        o[1] = dy * inv;
        o[2] = dz * inv;
    }
}

extern "C" void kernel_launch(void* const* d_in, const int* in_sizes, int n_in,
                              void* d_out, int out_size)
{
    const float* input    = (const float*)d_in[0];  // [B,N,C]
    const float* points   = (const float*)d_in[1];  // [B,N,3]
    const float* next_pts = (const float*)d_in[2];  // [B,M,3]
    const int*   indices  = (const int*)  d_in[3];  // [B,M,K]

    float* out_pts  = (float*)d_out;                         // B*M*K*3
    float* out_feat = out_pts + (size_t)BB * MM * KK * 3;    // B*M*K*C

    const int grid = BB * MM;   // 32768 CTAs
    knn_gather_norm_v16_kernel<<<grid, 128>>>(input, points, next_pts, indices,
                                              out_pts, out_feat);
}